// round 7
// baseline (speedup 1.0000x reference)
#include <cuda_runtime.h>
#include <cuda_bf16.h>
#include <cstdint>

#define N_NODES 2048
#define NQ (N_NODES / 4)            // 512 float4 per row
#define ROW_BYTES (N_NODES * 4)     // 8192 B per row
#define EPS 0.01f
#define THREADS 256
#define DEPTH 4
#define CHUNKS 74                   // per batch -> 8*74 = 592 CTAs = 148 SMs * 4
#define MAX_BLOCKS 4096

__device__ int g_partials[MAX_BLOCKS];
__device__ unsigned int g_arrive = 0;

__device__ __forceinline__ uint32_t smem_u32(const void* p) {
    return (uint32_t)__cvta_generic_to_shared(p);
}

__device__ __forceinline__ void mbar_init(uint32_t mbar, uint32_t count) {
    asm volatile("mbarrier.init.shared.b64 [%0], %1;" :: "r"(mbar), "r"(count) : "memory");
}

__device__ __forceinline__ void mbar_expect_tx(uint32_t mbar, uint32_t bytes) {
    asm volatile("mbarrier.arrive.expect_tx.shared.b64 _, [%0], %1;"
                 :: "r"(mbar), "r"(bytes) : "memory");
}

__device__ __forceinline__ void mbar_wait_parity(uint32_t mbar, uint32_t parity) {
    asm volatile(
        "{\n\t"
        ".reg .pred P;\n\t"
        "WAIT_%=:\n\t"
        "mbarrier.try_wait.parity.acquire.cta.shared::cta.b64 P, [%0], %1, 0x989680;\n\t"
        "@!P bra WAIT_%=;\n\t"
        "}"
        :: "r"(mbar), "r"(parity) : "memory");
}

__device__ __forceinline__ void tma_1d(uint32_t dst_smem, const void* src_gmem,
                                       uint32_t bytes, uint32_t mbar) {
    asm volatile(
        "cp.async.bulk.shared::cta.global.mbarrier::complete_tx::bytes [%0], [%1], %2, [%3];"
        :: "r"(dst_smem), "l"(src_gmem), "r"(bytes), "r"(mbar) : "memory");
}

__device__ __forceinline__ int pair4(const float4 w, const float pi, const float4 pj)
{
    int c = 0;
    c += (w.x == 1.0f) & (fabsf(pi - pj.x) < EPS);
    c += (w.y == 1.0f) & (fabsf(pi - pj.y) < EPS);
    c += (w.z == 1.0f) & (fabsf(pi - pj.z) < EPS);
    c += (w.w == 1.0f) & (fabsf(pi - pj.w) < EPS);
    return c;
}

__global__ void __launch_bounds__(THREADS, 4) count_kernel(
    const float* __restrict__ W, const float* __restrict__ pred,
    float* __restrict__ out, int nblocks)
{
    __shared__ float4 s_stage[DEPTH][NQ];            // 32 KB ring
    __shared__ float4 s_pred4[NQ];                   // 8 KB pred[b]
    __shared__ unsigned long long s_mbar[DEPTH];
    __shared__ int warpsum[THREADS / 32];
    __shared__ bool s_last;

    const int bid = blockIdx.x;
    const int b = bid / CHUNKS;
    const int c = bid % CHUNKS;
    const int start = (c * N_NODES) / CHUNKS;
    const int end   = ((c + 1) * N_NODES) / CHUNKS;
    const int n = end - start;                       // 27 or 28
    const int tid = threadIdx.x;

    // pred[b] -> smem
    const float4* predb4 = (const float4*)(pred + ((size_t)b << 11));
    for (int i = tid; i < NQ; i += THREADS)
        s_pred4[i] = predb4[i];

    const uint32_t mb0 = smem_u32(s_mbar);
    if (tid == 0) {
        #pragma unroll
        for (int s = 0; s < DEPTH; ++s)
            mbar_init(mb0 + 8 * s, 1);               // tx-based: 1 arrival via expect_tx
    }
    __syncthreads();

    // per-thread fixed column groups (registers)
    const float4 pj0 = s_pred4[tid];
    const float4 pj1 = s_pred4[tid + THREADS];
    const float* s_predf = (const float*)s_pred4;

    const float* Wrow0 = W + (size_t)(2 * b + 1) * (size_t)N_NODES * N_NODES
                         + (size_t)start * N_NODES;

    // prologue: fill the ring
    if (tid == 0) {
        const int pre = (n < DEPTH) ? n : DEPTH;
        for (int s = 0; s < pre; ++s) {
            mbar_expect_tx(mb0 + 8 * s, ROW_BYTES);
            tma_1d(smem_u32(s_stage[s]), Wrow0 + (size_t)s * N_NODES, ROW_BYTES, mb0 + 8 * s);
        }
    }

    int cnt = 0;
    for (int r = 0; r < n; ++r) {
        const int s = r & (DEPTH - 1);
        mbar_wait_parity(mb0 + 8 * s, (r >> 2) & 1);

        const float pi = s_predf[start + r];
        const float4 w0 = s_stage[s][tid];
        const float4 w1 = s_stage[s][tid + THREADS];
        cnt += pair4(w0, pi, pj0);
        cnt += pair4(w1, pi, pj1);

        __syncthreads();   // slot s fully consumed by all threads
        if (tid == 0 && r + DEPTH < n) {
            mbar_expect_tx(mb0 + 8 * s, ROW_BYTES);
            tma_1d(smem_u32(s_stage[s]), Wrow0 + (size_t)(r + DEPTH) * N_NODES,
                   ROW_BYTES, mb0 + 8 * s);
        }
    }

    // block reduce
    #pragma unroll
    for (int o = 16; o > 0; o >>= 1)
        cnt += __shfl_xor_sync(0xffffffffu, cnt, o);

    if ((tid & 31) == 0)
        warpsum[tid >> 5] = cnt;
    __syncthreads();

    if (tid == 0) {
        int v = 0;
        #pragma unroll
        for (int i = 0; i < THREADS / 32; ++i)
            v += warpsum[i];
        g_partials[bid] = v;
        __threadfence();
        unsigned int old = atomicAdd(&g_arrive, 1u);
        s_last = (old == (unsigned)(nblocks - 1));
    }
    __syncthreads();

    // last CTA finalizes
    if (s_last) {
        int v = 0;
        for (int i = tid; i < nblocks; i += THREADS)
            v += g_partials[i];
        #pragma unroll
        for (int o = 16; o > 0; o >>= 1)
            v += __shfl_xor_sync(0xffffffffu, v, o);
        if ((tid & 31) == 0)
            warpsum[tid >> 5] = v;
        __syncthreads();
        if (tid == 0) {
            int t = 0;
            #pragma unroll
            for (int i = 0; i < THREADS / 32; ++i)
                t += warpsum[i];
            out[0] = (float)t;
            g_arrive = 0;   // reset for next graph replay
        }
    }
}

extern "C" void kernel_launch(void* const* d_in, const int* in_sizes, int n_in,
                              void* d_out, int out_size)
{
    const float* W    = (const float*)d_in[0];
    const float* pred = (const float*)d_in[1];
    float* out = (float*)d_out;

    const int B = in_sizes[1] / N_NODES;
    const int nblocks = B * CHUNKS;     // 592
    count_kernel<<<nblocks, THREADS>>>(W, pred, out, nblocks);
}

// round 8
// speedup vs baseline: 1.0931x; 1.0931x over previous
#include <cuda_runtime.h>
#include <cuda_bf16.h>
#include <cstdint>

#define N_NODES 2048
#define NQ (N_NODES / 4)          // 512 float4 per row
#define EPS 0.01f
#define THREADS 256
#define CHUNKS 74                 // per batch -> 8*74 = 592 CTAs = 148 SMs * 4

__device__ unsigned long long g_combined = 0ULL;  // [arrivals:32 | count:32]

__device__ __forceinline__ int pair4(const float4 w, const float pi, const float4 pj)
{
    int c = 0;
    c += (w.x == 1.0f) & (fabsf(pi - pj.x) < EPS);
    c += (w.y == 1.0f) & (fabsf(pi - pj.y) < EPS);
    c += (w.z == 1.0f) & (fabsf(pi - pj.z) < EPS);
    c += (w.w == 1.0f) & (fabsf(pi - pj.w) < EPS);
    return c;
}

__global__ void __launch_bounds__(THREADS, 4) count_kernel(
    const float* __restrict__ W, const float* __restrict__ pred,
    float* __restrict__ out, int nblocks)
{
    const int bid = blockIdx.x;
    const int b   = bid / CHUNKS;
    const int c   = bid % CHUNKS;
    const int start = (c * N_NODES) / CHUNKS;
    const int end   = ((c + 1) * N_NODES) / CHUNKS;   // 27 or 28 rows, same batch
    const int tid = threadIdx.x;

    const float* predb = pred + ((size_t)b << 11);
    const float4* Wt = (const float4*)(W + (size_t)(2 * b + 1) * (size_t)N_NODES * N_NODES)
                       + (size_t)start * NQ + tid;

    // --- prologue: start the W stream FIRST (DRAM busy from cycle ~0) ---
    float4 w0[2], w1[2];
    float  pi[2];
    w0[0] = __ldcs(Wt);
    w1[0] = __ldcs(Wt + THREADS);

    // per-thread fixed column groups (L2-hot after first CTA of each batch)
    const float4 pj0 = __ldg((const float4*)predb + tid);
    const float4 pj1 = __ldg((const float4*)predb + tid + THREADS);
    pi[0] = __ldg(predb + start);

    int cnt = 0;
    int p = 0;
    #pragma unroll 2
    for (int r = start; r < end; ++r) {
        const int nxt = p ^ 1;
        if (r + 1 < end) {
            const float4* wn = Wt + (size_t)(r + 1 - start) * NQ;
            w0[nxt] = __ldcs(wn);
            w1[nxt] = __ldcs(wn + THREADS);
            pi[nxt] = __ldg(predb + r + 1);
        }
        cnt += pair4(w0[p], pi[p], pj0);
        cnt += pair4(w1[p], pi[p], pj1);
        p = nxt;
    }

    // block reduce
    #pragma unroll
    for (int o = 16; o > 0; o >>= 1)
        cnt += __shfl_xor_sync(0xffffffffu, cnt, o);

    __shared__ int warpsum[THREADS / 32];
    if ((tid & 31) == 0)
        warpsum[tid >> 5] = cnt;
    __syncthreads();

    if (tid == 0) {
        int v = 0;
        #pragma unroll
        for (int i = 0; i < THREADS / 32; ++i)
            v += warpsum[i];
        // one packed RMW: arrivals in high 32, count in low 32. The RMW total
        // order guarantees the last arriver's returned value holds the full
        // partial sum of all other CTAs — no fence, no partials array.
        unsigned long long old =
            atomicAdd(&g_combined, (1ULL << 32) | (unsigned long long)(unsigned)v);
        if ((unsigned)(old >> 32) == (unsigned)(nblocks - 1)) {
            const unsigned total = (unsigned)old + (unsigned)v;
            out[0] = (float)total;
            g_combined = 0ULL;   // reset for next graph replay (deterministic)
        }
    }
}

extern "C" void kernel_launch(void* const* d_in, const int* in_sizes, int n_in,
                              void* d_out, int out_size)
{
    const float* W    = (const float*)d_in[0];
    const float* pred = (const float*)d_in[1];
    float* out = (float*)d_out;

    const int B = in_sizes[1] / N_NODES;
    const int nblocks = B * CHUNKS;     // 592
    count_kernel<<<nblocks, THREADS>>>(W, pred, out, nblocks);
}